// round 1
// baseline (speedup 1.0000x reference)
#include <cuda_runtime.h>
#include <math.h>

#define BB 4
#define CC 256
#define MID 64
#define HWN 4096
#define EPSV 1e-5f

// ---------------- scratch (device globals; no allocation allowed) ----------
__device__ float g_Wcat[192 * CC];        // folded [f;g;h] weights, BN-folded
__device__ float g_bcat[192];             // folded biases
__device__ float g_FGH[(size_t)BB * 192 * HWN];  // rows 0-63: F, 64-127: G, 128-191: H
__device__ float g_gv[BB * MID];          // G @ v0
__device__ float g_vun[BB * HWN];         // unnormalized v = F^T (G v0)
__device__ float g_ss[BB];                // ||v_un||^2
__device__ float g_fv[BB * MID];          // F @ v_un
__device__ float g_gvv[BB * MID];         // G @ v_un
__device__ float g_s[BB];                 // spectral estimate s
__device__ float g_M[BB * MID * MID];     // M[k][c] = sum_m G[k,m] H[c,m]
__device__ float g_Q[(size_t)BB * CC * MID]; // Q = Wv @ M^T / s

// ---------------- reductions ----------------
__device__ __forceinline__ float warpSum(float v) {
#pragma unroll
    for (int o = 16; o > 0; o >>= 1) v += __shfl_xor_sync(0xffffffffu, v, o);
    return v;
}

__device__ __forceinline__ float blockSum(float v) {
    __shared__ float sm[32];
    int lane = threadIdx.x & 31, w = threadIdx.x >> 5;
    v = warpSum(v);
    if (lane == 0) sm[w] = v;
    __syncthreads();
    int nw = (blockDim.x + 31) >> 5;
    v = (threadIdx.x < nw) ? sm[threadIdx.x] : 0.f;
    if (w == 0) v = warpSum(v);
    return v;  // valid in thread 0
}

// ---------------- kernel 0: fold BN into weights, zero accumulators --------
__global__ void k_prep(const float* __restrict__ Wf, const float* __restrict__ bf,
                       const float* __restrict__ gaf, const float* __restrict__ bef,
                       const float* __restrict__ mef, const float* __restrict__ vaf,
                       const float* __restrict__ Wg, const float* __restrict__ bg,
                       const float* __restrict__ gag, const float* __restrict__ beg,
                       const float* __restrict__ meg, const float* __restrict__ vag,
                       const float* __restrict__ Wh, const float* __restrict__ bh) {
    int idx = blockIdx.x * blockDim.x + threadIdx.x;
    if (idx < BB * MID * MID) g_M[idx] = 0.f;
    if (idx < BB) g_ss[idx] = 0.f;
    if (idx >= 192 * CC) return;
    int o = idx / CC, c = idx % CC;
    float w, bias;
    if (o < 64) {
        float inv = gaf[o] * rsqrtf(vaf[o] + EPSV);
        w = Wf[o * CC + c] * inv;
        bias = bf[o] * inv + bef[o] - mef[o] * inv;
    } else if (o < 128) {
        int oo = o - 64;
        float inv = gag[oo] * rsqrtf(vag[oo] + EPSV);
        w = Wg[oo * CC + c] * inv;
        bias = bg[oo] * inv + beg[oo] - meg[oo] * inv;
    } else {
        int oo = o - 128;
        w = Wh[oo * CC + c];
        bias = bh[oo];
    }
    g_Wcat[idx] = w;
    if (c == 0) g_bcat[o] = bias;
}

// ---------------- kernel 1: FGH = relu?(Wcat @ x + bcat) --------------------
// grid (HW/64, 3, B), block 256; 64x64 tile, 4x4 microtile, BK=64
__global__ __launch_bounds__(256) void k_fgh(const float* __restrict__ x) {
    __shared__ float As[64][65];  // As[m][k], pad avoids STS conflicts
    __shared__ float Bs[64][64];  // Bs[k][n]
    int b = blockIdx.z;
    int rowBase = blockIdx.y * 64;
    int nBase = blockIdx.x * 64;
    int tid = threadIdx.x;
    int tx = tid & 15, ty = tid >> 4;
    const float* xb = x + (size_t)b * CC * HWN;
    float acc[4][4] = {};

    for (int kt = 0; kt < CC; kt += 64) {
#pragma unroll
        for (int r = 0; r < 4; r++) {
            int m = (tid >> 4) + r * 16;
            int k4 = (tid & 15) * 4;
            float4 a = *(const float4*)&g_Wcat[(size_t)(rowBase + m) * CC + kt + k4];
            As[m][k4 + 0] = a.x; As[m][k4 + 1] = a.y; As[m][k4 + 2] = a.z; As[m][k4 + 3] = a.w;
            float4 bv4 = *(const float4*)&xb[(size_t)(kt + m) * HWN + nBase + k4];
            *(float4*)&Bs[m][k4] = bv4;
        }
        __syncthreads();
#pragma unroll
        for (int k = 0; k < 64; k++) {
            float av[4];
#pragma unroll
            for (int i = 0; i < 4; i++) av[i] = As[ty * 4 + i][k];
            float4 bq = *(const float4*)&Bs[k][tx * 4];
            float bw[4] = {bq.x, bq.y, bq.z, bq.w};
#pragma unroll
            for (int i = 0; i < 4; i++)
#pragma unroll
                for (int j = 0; j < 4; j++) acc[i][j] += av[i] * bw[j];
        }
        __syncthreads();
    }
#pragma unroll
    for (int i = 0; i < 4; i++) {
        int orow = rowBase + ty * 4 + i;
        float bias = g_bcat[orow];
        float4 v;
        v.x = acc[i][0] + bias; v.y = acc[i][1] + bias;
        v.z = acc[i][2] + bias; v.w = acc[i][3] + bias;
        if (orow < 128) {
            v.x = fmaxf(v.x, 0.f); v.y = fmaxf(v.y, 0.f);
            v.z = fmaxf(v.z, 0.f); v.w = fmaxf(v.w, 0.f);
        }
        *(float4*)&g_FGH[((size_t)b * 192 + orow) * HWN + nBase + tx * 4] = v;
    }
}

// ---------------- kernel 2: gv = G @ v0 -------------------------------------
__global__ void k_gv(const float* __restrict__ v0) {
    int b = blockIdx.x, k = blockIdx.y;
    const float* row = g_FGH + ((size_t)b * 192 + 64 + k) * HWN;
    const float* v = v0 + (size_t)b * HWN;
    float s = 0.f;
    for (int n = threadIdx.x; n < HWN; n += blockDim.x) s += row[n] * v[n];
    s = blockSum(s);
    if (threadIdx.x == 0) g_gv[b * MID + k] = s;
}

// ---------------- kernel 3: v_un = F^T gv ; ss = ||v_un||^2 ------------------
__global__ void k_vun() {
    int b = blockIdx.y;
    int n = blockIdx.x * 256 + threadIdx.x;
    __shared__ float gvs[64];
    if (threadIdx.x < 64) gvs[threadIdx.x] = g_gv[b * MID + threadIdx.x];
    __syncthreads();
    const float* Fb = g_FGH + (size_t)b * 192 * HWN;
    float s = 0.f;
#pragma unroll
    for (int k = 0; k < 64; k++) s += Fb[(size_t)k * HWN + n] * gvs[k];
    g_vun[(size_t)b * HWN + n] = s;
    float q = blockSum(s * s);
    if (threadIdx.x == 0) atomicAdd(&g_ss[b], q);
}

// ---------------- kernel 4: fv = F v_un ; gvv = G v_un -----------------------
__global__ void k_fvgvv() {
    int b = blockIdx.x, r = blockIdx.y;  // r in [0,128): row r of FGH (F then G)
    const float* row = g_FGH + ((size_t)b * 192 + r) * HWN;
    const float* v = g_vun + (size_t)b * HWN;
    float s = 0.f;
    for (int n = threadIdx.x; n < HWN; n += blockDim.x) s += row[n] * v[n];
    s = blockSum(s);
    if (threadIdx.x == 0) {
        if (r < 64) g_fv[b * MID + r] = s;
        else g_gvv[b * MID + (r - 64)] = s;
    }
}

// ---------------- kernel 5: s = (fv . gvv) / ss ------------------------------
__global__ void k_s() {
    int b = blockIdx.x;
    float p = 0.f;
    for (int k = threadIdx.x; k < 64; k += 32) p += g_fv[b * MID + k] * g_gvv[b * MID + k];
    p = warpSum(p);
    if (threadIdx.x == 0) g_s[b] = p / g_ss[b];
}

// ---------------- kernel 6: M = G @ H^T (split-K, atomic accumulation) ------
// grid (B, 64); each block handles a K-chunk of 64 columns of HW
__global__ __launch_bounds__(256) void k_M() {
    __shared__ float Gs[64][33];
    __shared__ float Hs[64][33];
    int b = blockIdx.x;
    int kbase = blockIdx.y * 64;
    int tid = threadIdx.x, tx = tid & 15, ty = tid >> 4;
    const float* Gb = g_FGH + ((size_t)b * 192 + 64) * HWN;
    const float* Hb = g_FGH + ((size_t)b * 192 + 128) * HWN;
    float acc[4][4] = {};
    for (int kk = 0; kk < 64; kk += 32) {
#pragma unroll
        for (int r = 0; r < 2; r++) {
            int row = (tid >> 3) + r * 32;
            int c4 = (tid & 7) * 4;
            float4 gq = *(const float4*)&Gb[(size_t)row * HWN + kbase + kk + c4];
            Gs[row][c4 + 0] = gq.x; Gs[row][c4 + 1] = gq.y; Gs[row][c4 + 2] = gq.z; Gs[row][c4 + 3] = gq.w;
            float4 hq = *(const float4*)&Hb[(size_t)row * HWN + kbase + kk + c4];
            Hs[row][c4 + 0] = hq.x; Hs[row][c4 + 1] = hq.y; Hs[row][c4 + 2] = hq.z; Hs[row][c4 + 3] = hq.w;
        }
        __syncthreads();
#pragma unroll
        for (int k = 0; k < 32; k++) {
            float gw[4], hw[4];
#pragma unroll
            for (int i = 0; i < 4; i++) gw[i] = Gs[ty * 4 + i][k];
#pragma unroll
            for (int j = 0; j < 4; j++) hw[j] = Hs[tx * 4 + j][k];
#pragma unroll
            for (int i = 0; i < 4; i++)
#pragma unroll
                for (int j = 0; j < 4; j++) acc[i][j] += gw[i] * hw[j];
        }
        __syncthreads();
    }
#pragma unroll
    for (int i = 0; i < 4; i++)
#pragma unroll
        for (int j = 0; j < 4; j++)
            atomicAdd(&g_M[((size_t)b * MID + ty * 4 + i) * MID + tx * 4 + j], acc[i][j]);
}

// ---------------- kernel 7a: Q = (Wv @ M^T) / s ------------------------------
// grid (B, 64): block handles one k-column of Q; 256 threads = 256 output rows
__global__ void k_Q(const float* __restrict__ Wv) {
    int b = blockIdx.x, k = blockIdx.y, o = threadIdx.x;
    __shared__ float Ms[64];
    if (o < 64) Ms[o] = g_M[((size_t)b * MID + k) * MID + o];
    __syncthreads();
    float inv_s = 1.f / g_s[b];
    float acc = 0.f;
#pragma unroll
    for (int c = 0; c < 64; c++) acc += Wv[o * MID + c] * Ms[c];
    g_Q[((size_t)b * CC + o) * MID + k] = acc * inv_s;
}

// ---------------- kernel 7b: out = Q @ F + bv + x ----------------------------
// grid (HW/64, C/64, B), block 256; single K-tile (K=64)
__global__ __launch_bounds__(256) void k_out(const float* __restrict__ x,
                                             const float* __restrict__ bv,
                                             float* __restrict__ out) {
    __shared__ float As[64][65];
    __shared__ float Bs[64][64];
    int b = blockIdx.z;
    int rowBase = blockIdx.y * 64;
    int nBase = blockIdx.x * 64;
    int tid = threadIdx.x;
    int tx = tid & 15, ty = tid >> 4;
    const float* Qb = g_Q + (size_t)b * CC * MID;
    const float* Fb = g_FGH + (size_t)b * 192 * HWN;
    float acc[4][4] = {};

#pragma unroll
    for (int r = 0; r < 4; r++) {
        int m = (tid >> 4) + r * 16;
        int k4 = (tid & 15) * 4;
        float4 a = *(const float4*)&Qb[(size_t)(rowBase + m) * MID + k4];
        As[m][k4 + 0] = a.x; As[m][k4 + 1] = a.y; As[m][k4 + 2] = a.z; As[m][k4 + 3] = a.w;
        float4 bq = *(const float4*)&Fb[(size_t)m * HWN + nBase + k4];
        *(float4*)&Bs[m][k4] = bq;
    }
    __syncthreads();
#pragma unroll
    for (int k = 0; k < 64; k++) {
        float av[4];
#pragma unroll
        for (int i = 0; i < 4; i++) av[i] = As[ty * 4 + i][k];
        float4 bq = *(const float4*)&Bs[k][tx * 4];
        float bw[4] = {bq.x, bq.y, bq.z, bq.w};
#pragma unroll
        for (int i = 0; i < 4; i++)
#pragma unroll
            for (int j = 0; j < 4; j++) acc[i][j] += av[i] * bw[j];
    }
#pragma unroll
    for (int i = 0; i < 4; i++) {
        int orow = rowBase + ty * 4 + i;
        float bias = bv[orow];
        size_t off = ((size_t)b * CC + orow) * HWN + nBase + tx * 4;
        float4 xr = *(const float4*)&x[off];
        float4 v;
        v.x = acc[i][0] + bias + xr.x;
        v.y = acc[i][1] + bias + xr.y;
        v.z = acc[i][2] + bias + xr.z;
        v.w = acc[i][3] + bias + xr.w;
        *(float4*)&out[off] = v;
    }
}

// ---------------- launch ----------------
extern "C" void kernel_launch(void* const* d_in, const int* in_sizes, int n_in,
                              void* d_out, int out_size) {
    (void)in_sizes; (void)n_in; (void)out_size;
    const float* x   = (const float*)d_in[0];
    const float* Wf  = (const float*)d_in[1];
    const float* bf  = (const float*)d_in[2];
    const float* gaf = (const float*)d_in[3];
    const float* bef = (const float*)d_in[4];
    const float* mef = (const float*)d_in[5];
    const float* vaf = (const float*)d_in[6];
    const float* Wg  = (const float*)d_in[7];
    const float* bg  = (const float*)d_in[8];
    const float* gag = (const float*)d_in[9];
    const float* beg = (const float*)d_in[10];
    const float* meg = (const float*)d_in[11];
    const float* vag = (const float*)d_in[12];
    const float* Wh  = (const float*)d_in[13];
    const float* bh  = (const float*)d_in[14];
    const float* Wv  = (const float*)d_in[15];
    const float* bv  = (const float*)d_in[16];
    const float* v0  = (const float*)d_in[17];
    float* out = (float*)d_out;

    k_prep<<<(192 * CC + 255) / 256, 256>>>(Wf, bf, gaf, bef, mef, vaf,
                                            Wg, bg, gag, beg, meg, vag, Wh, bh);
    k_fgh<<<dim3(HWN / 64, 3, BB), 256>>>(x);
    k_gv<<<dim3(BB, MID), 128>>>(v0);
    k_vun<<<dim3(HWN / 256, BB), 256>>>();
    k_fvgvv<<<dim3(BB, 128), 128>>>();
    k_s<<<BB, 32>>>();
    k_M<<<dim3(BB, 64), 256>>>();
    k_Q<<<dim3(BB, 64), 256>>>(Wv);
    k_out<<<dim3(HWN / 64, CC / 64, BB), 256>>>(x, bv, out);
}

// round 4
// speedup vs baseline: 1.2807x; 1.2807x over previous
#include <cuda_runtime.h>
#include <cuda_bf16.h>
#include <cstdint>
#include <stdint.h>
#include <math.h>

#define BB 4
#define CC 256
#define MID 64
#define HWN 4096
#define EPSV 1e-5f

// ---------------- scratch (device globals; no allocation allowed) ----------
__device__ __nv_bfloat16 g_Whi[192 * CC];   // folded [f;g;h] weights, bf16 hi
__device__ __nv_bfloat16 g_Wlo[192 * CC];   // bf16 lo residual
__device__ float g_bcat[192];               // folded biases
__device__ __nv_bfloat16 g_Xhi[(size_t)BB * HWN * CC];  // x^T bf16 hi: [b][n][c]
__device__ __nv_bfloat16 g_Xlo[(size_t)BB * HWN * CC];  // x^T bf16 lo
__device__ float g_FGH[(size_t)BB * 192 * HWN];  // rows 0-63: F, 64-127: G, 128-191: H
__device__ float g_gv[BB * MID];            // G @ v0
__device__ float g_vun[BB * HWN];           // unnormalized v = F^T (G v0)
__device__ float g_ss[BB];                  // ||v_un||^2
__device__ float g_fv[BB * MID];            // F @ v_un
__device__ float g_gvv[BB * MID];           // G @ v_un
__device__ float g_s[BB];                   // spectral estimate s
__device__ float g_M[BB * MID * MID];       // M[k][c] = sum_m G[k,m] H[c,m]
__device__ float g_Q[(size_t)BB * CC * MID]; // Q = Wv @ M^T / s

// ---------------- mma.sync helper (bf16, f32 accum) -------------------------
__device__ __forceinline__ void mma16816(float& c0, float& c1, float& c2, float& c3,
                                         uint32_t a0, uint32_t a1, uint32_t a2, uint32_t a3,
                                         uint32_t b0, uint32_t b1) {
    asm volatile(
        "mma.sync.aligned.m16n8k16.row.col.f32.bf16.bf16.f32 "
        "{%0,%1,%2,%3}, {%4,%5,%6,%7}, {%8,%9}, {%0,%1,%2,%3};"
        : "+f"(c0), "+f"(c1), "+f"(c2), "+f"(c3)
        : "r"(a0), "r"(a1), "r"(a2), "r"(a3), "r"(b0), "r"(b1));
}

// ---------------- reductions ----------------
__device__ __forceinline__ float warpSum(float v) {
#pragma unroll
    for (int o = 16; o > 0; o >>= 1) v += __shfl_xor_sync(0xffffffffu, v, o);
    return v;
}
__device__ __forceinline__ float blockSum(float v) {
    __shared__ float sm[32];
    int lane = threadIdx.x & 31, w = threadIdx.x >> 5;
    v = warpSum(v);
    if (lane == 0) sm[w] = v;
    __syncthreads();
    int nw = (blockDim.x + 31) >> 5;
    v = (threadIdx.x < nw) ? sm[threadIdx.x] : 0.f;
    if (w == 0) v = warpSum(v);
    return v;
}

// ---------------- kernel 0: fold BN, split weights to bf16 hi/lo ------------
__global__ void k_prep(const float* __restrict__ Wf, const float* __restrict__ bf,
                       const float* __restrict__ gaf, const float* __restrict__ bef,
                       const float* __restrict__ mef, const float* __restrict__ vaf,
                       const float* __restrict__ Wg, const float* __restrict__ bg,
                       const float* __restrict__ gag, const float* __restrict__ beg,
                       const float* __restrict__ meg, const float* __restrict__ vag,
                       const float* __restrict__ Wh, const float* __restrict__ bh) {
    int idx = blockIdx.x * blockDim.x + threadIdx.x;
    if (idx < BB * MID * MID) g_M[idx] = 0.f;
    if (idx < BB) g_ss[idx] = 0.f;
    if (idx >= 192 * CC) return;
    int o = idx / CC, c = idx % CC;
    float w, bias;
    if (o < 64) {
        float inv = gaf[o] * rsqrtf(vaf[o] + EPSV);
        w = Wf[o * CC + c] * inv;
        bias = bf[o] * inv + bef[o] - mef[o] * inv;
    } else if (o < 128) {
        int oo = o - 64;
        float inv = gag[oo] * rsqrtf(vag[oo] + EPSV);
        w = Wg[oo * CC + c] * inv;
        bias = bg[oo] * inv + beg[oo] - meg[oo] * inv;
    } else {
        int oo = o - 128;
        w = Wh[oo * CC + c];
        bias = bh[oo];
    }
    __nv_bfloat16 hi = __float2bfloat16(w);
    __nv_bfloat16 lo = __float2bfloat16(w - __bfloat162float(hi));
    g_Whi[idx] = hi;
    g_Wlo[idx] = lo;
    if (c == 0) g_bcat[o] = bias;
}

// ---------------- kernel 0b: transpose + split x to bf16 hi/lo --------------
// x [b][c][n] fp32 -> g_Xhi/g_Xlo [b][n][c] bf16
__global__ void k_xsplit(const float* __restrict__ x) {
    __shared__ float t[32][33];
    int b = blockIdx.z;
    int ct = blockIdx.y * 32, nt = blockIdx.x * 32;
    int tx = threadIdx.x, ty = threadIdx.y;
    const float* xb = x + (size_t)b * CC * HWN;
#pragma unroll
    for (int j = 0; j < 32; j += 8)
        t[ty + j][tx] = xb[(size_t)(ct + ty + j) * HWN + nt + tx];
    __syncthreads();
#pragma unroll
    for (int j = 0; j < 32; j += 8) {
        float v = t[tx][ty + j];
        __nv_bfloat16 hi = __float2bfloat16(v);
        __nv_bfloat16 lo = __float2bfloat16(v - __bfloat162float(hi));
        size_t o = ((size_t)b * HWN + nt + ty + j) * CC + ct + tx;
        g_Xhi[o] = hi;
        g_Xlo[o] = lo;
    }
}

// ---------------- kernel 1: FGH via mma.sync bf16-split GEMM ----------------
// grid (HW/128, 3, B), 256 threads (8 warps, 2x4 warp grid).
// CTA tile: M=64 (FGH rows), N=128 (pixels); warp tile 32x32.
// K = 256 in chunks of 64; 3 split passes (Whi*Xhi + Wlo*Xhi + Whi*Xlo).
#define SAS 72   // smem row stride in bf16 (144 B: 16B-aligned, conflict-free)
__global__ __launch_bounds__(256) void k_fgh_mma() {
    __shared__ __nv_bfloat16 As[64 * SAS];
    __shared__ __nv_bfloat16 Bs[128 * SAS];
    int tid = threadIdx.x;
    int wid = tid >> 5, lane = tid & 31;
    int b = blockIdx.z, mt = blockIdx.y;
    int nbase = blockIdx.x * 128;
    int wm = wid & 1, wn = wid >> 1;     // warp tile: rows wm*32.., cols wn*32..

    const __nv_bfloat16* Xh = g_Xhi + (size_t)b * HWN * CC;
    const __nv_bfloat16* Xl = g_Xlo + (size_t)b * HWN * CC;

    float acc[2][4][4];
#pragma unroll
    for (int i = 0; i < 2; i++)
#pragma unroll
        for (int j = 0; j < 4; j++)
#pragma unroll
            for (int q = 0; q < 4; q++) acc[i][j][q] = 0.f;

    int r = lane >> 2;          // 0..7
    int kp = (lane & 3) * 2;    // 0,2,4,6

#pragma unroll 1
    for (int p = 0; p < 3; p++) {
        const __nv_bfloat16* Ag = (p == 1) ? g_Wlo : g_Whi;
        const __nv_bfloat16* Bg = (p == 2) ? Xl : Xh;
#pragma unroll 1
        for (int kt = 0; kt < CC; kt += 64) {
            // fill A: 64x64 bf16 = 512 uint4 (2/thread)
#pragma unroll
            for (int i = 0; i < 2; i++) {
                int unit = i * 256 + tid;
                int row = unit >> 3, uc = unit & 7;
                const uint4 v = *(const uint4*)(Ag + (size_t)(mt * 64 + row) * CC + kt + uc * 8);
                *(uint4*)(As + row * SAS + uc * 8) = v;
            }
            // fill B: 128x64 bf16 = 1024 uint4 (4/thread)
#pragma unroll
            for (int i = 0; i < 4; i++) {
                int unit = i * 256 + tid;
                int row = unit >> 3, uc = unit & 7;
                const uint4 v = *(const uint4*)(Bg + (size_t)(nbase + row) * CC + kt + uc * 8);
                *(uint4*)(Bs + row * SAS + uc * 8) = v;
            }
            __syncthreads();
#pragma unroll
            for (int ks = 0; ks < 4; ks++) {
                int k0 = ks * 16;
                uint32_t af[2][4], bfr[4][2];
#pragma unroll
                for (int mf = 0; mf < 2; mf++) {
                    const __nv_bfloat16* ap = As + (wm * 32 + mf * 16 + r) * SAS + k0 + kp;
                    af[mf][0] = *(const uint32_t*)(ap);
                    af[mf][1] = *(const uint32_t*)(ap + 8 * SAS);
                    af[mf][2] = *(const uint32_t*)(ap + 8);
                    af[mf][3] = *(const uint32_t*)(ap + 8 * SAS + 8);
                }
#pragma unroll
                for (int nf = 0; nf < 4; nf++) {
                    const __nv_bfloat16* bp = Bs + (wn * 32 + nf * 8 + r) * SAS + k0 + kp;
                    bfr[nf][0] = *(const uint32_t*)(bp);
                    bfr[nf][1] = *(const uint32_t*)(bp + 8);
                }
#pragma unroll
                for (int mf = 0; mf < 2; mf++)
#pragma unroll
                    for (int nf = 0; nf < 4; nf++)
                        mma16816(acc[mf][nf][0], acc[mf][nf][1], acc[mf][nf][2], acc[mf][nf][3],
                                 af[mf][0], af[mf][1], af[mf][2], af[mf][3],
                                 bfr[nf][0], bfr[nf][1]);
            }
            __syncthreads();
        }
    }

    // epilogue: c0,c1 -> (row rq, col cq, cq+1); c2,c3 -> (row rq+8)
    int rq = lane >> 2;
    int cq = (lane & 3) * 2;
#pragma unroll
    for (int mf = 0; mf < 2; mf++) {
#pragma unroll
        for (int half = 0; half < 2; half++) {
            int orow = mt * 64 + wm * 32 + mf * 16 + rq + half * 8;
            float bias = g_bcat[orow];
            bool rl = (orow < 128);
            float* dst = &g_FGH[((size_t)b * 192 + orow) * HWN + nbase + wn * 32];
#pragma unroll
            for (int nf = 0; nf < 4; nf++) {
                float2 v;
                v.x = acc[mf][nf][half * 2 + 0] + bias;
                v.y = acc[mf][nf][half * 2 + 1] + bias;
                if (rl) { v.x = fmaxf(v.x, 0.f); v.y = fmaxf(v.y, 0.f); }
                *(float2*)(dst + nf * 8 + cq) = v;
            }
        }
    }
}

// ---------------- kernel 2: gv = G @ v0 -------------------------------------
__global__ void k_gv(const float* __restrict__ v0) {
    int b = blockIdx.x, k = blockIdx.y;
    const float* row = g_FGH + ((size_t)b * 192 + 64 + k) * HWN;
    const float* v = v0 + (size_t)b * HWN;
    float s = 0.f;
    for (int n = threadIdx.x; n < HWN; n += blockDim.x) s += row[n] * v[n];
    s = blockSum(s);
    if (threadIdx.x == 0) g_gv[b * MID + k] = s;
}

// ---------------- kernel 3: v_un = F^T gv ; ss = ||v_un||^2 ------------------
__global__ void k_vun() {
    int b = blockIdx.y;
    int n = blockIdx.x * 128 + threadIdx.x;
    __shared__ float gvs[64];
    if (threadIdx.x < 64) gvs[threadIdx.x] = g_gv[b * MID + threadIdx.x];
    __syncthreads();
    const float* Fb = g_FGH + (size_t)b * 192 * HWN;
    float s = 0.f;
#pragma unroll
    for (int k = 0; k < 64; k++) s += Fb[(size_t)k * HWN + n] * gvs[k];
    g_vun[(size_t)b * HWN + n] = s;
    float q = blockSum(s * s);
    if (threadIdx.x == 0) atomicAdd(&g_ss[b], q);
}

// ---------------- kernel 4: fv = F v_un ; gvv = G v_un -----------------------
__global__ void k_fvgvv() {
    int b = blockIdx.x, r = blockIdx.y;
    const float* row = g_FGH + ((size_t)b * 192 + r) * HWN;
    const float* v = g_vun + (size_t)b * HWN;
    float s = 0.f;
    for (int n = threadIdx.x; n < HWN; n += blockDim.x) s += row[n] * v[n];
    s = blockSum(s);
    if (threadIdx.x == 0) {
        if (r < 64) g_fv[b * MID + r] = s;
        else g_gvv[b * MID + (r - 64)] = s;
    }
}

// ---------------- kernel 5: s = (fv . gvv) / ss ------------------------------
__global__ void k_s() {
    int b = blockIdx.x;
    float p = 0.f;
    for (int k = threadIdx.x; k < 64; k += 32) p += g_fv[b * MID + k] * g_gvv[b * MID + k];
    p = warpSum(p);
    if (threadIdx.x == 0) g_s[b] = p / g_ss[b];
}

// ---------------- kernel 6: M = G @ H^T (split-K, atomic accumulation) ------
__global__ __launch_bounds__(256) void k_M() {
    __shared__ float Gs[64][33];
    __shared__ float Hs[64][33];
    int b = blockIdx.x;
    int kbase = blockIdx.y * 64;
    int tid = threadIdx.x, tx = tid & 15, ty = tid >> 4;
    const float* Gb = g_FGH + ((size_t)b * 192 + 64) * HWN;
    const float* Hb = g_FGH + ((size_t)b * 192 + 128) * HWN;
    float acc[4][4] = {};
    for (int kk = 0; kk < 64; kk += 32) {
#pragma unroll
        for (int r = 0; r < 2; r++) {
            int row = (tid >> 3) + r * 32;
            int c4 = (tid & 7) * 4;
            float4 gq = *(const float4*)&Gb[(size_t)row * HWN + kbase + kk + c4];
            Gs[row][c4 + 0] = gq.x; Gs[row][c4 + 1] = gq.y; Gs[row][c4 + 2] = gq.z; Gs[row][c4 + 3] = gq.w;
            float4 hq = *(const float4*)&Hb[(size_t)row * HWN + kbase + kk + c4];
            Hs[row][c4 + 0] = hq.x; Hs[row][c4 + 1] = hq.y; Hs[row][c4 + 2] = hq.z; Hs[row][c4 + 3] = hq.w;
        }
        __syncthreads();
#pragma unroll
        for (int k = 0; k < 32; k++) {
            float gw[4], hw[4];
#pragma unroll
            for (int i = 0; i < 4; i++) gw[i] = Gs[ty * 4 + i][k];
#pragma unroll
            for (int j = 0; j < 4; j++) hw[j] = Hs[tx * 4 + j][k];
#pragma unroll
            for (int i = 0; i < 4; i++)
#pragma unroll
                for (int j = 0; j < 4; j++) acc[i][j] += gw[i] * hw[j];
        }
        __syncthreads();
    }
#pragma unroll
    for (int i = 0; i < 4; i++)
#pragma unroll
        for (int j = 0; j < 4; j++)
            atomicAdd(&g_M[((size_t)b * MID + ty * 4 + i) * MID + tx * 4 + j], acc[i][j]);
}

// ---------------- kernel 7a: Q = (Wv @ M^T) / s ------------------------------
__global__ void k_Q(const float* __restrict__ Wv) {
    int b = blockIdx.x, k = blockIdx.y, o = threadIdx.x;
    __shared__ float Ms[64];
    if (o < 64) Ms[o] = g_M[((size_t)b * MID + k) * MID + o];
    __syncthreads();
    float inv_s = 1.f / g_s[b];
    float acc = 0.f;
#pragma unroll
    for (int c = 0; c < 64; c++) acc += Wv[o * MID + c] * Ms[c];
    g_Q[((size_t)b * CC + o) * MID + k] = acc * inv_s;
}

// ---------------- kernel 7b: out = Q @ F + bv + x ----------------------------
__global__ __launch_bounds__(256) void k_out(const float* __restrict__ x,
                                             const float* __restrict__ bv,
                                             float* __restrict__ out) {
    __shared__ float As2[64][65];
    __shared__ float Bs2[64][64];
    int b = blockIdx.z;
    int rowBase = blockIdx.y * 64;
    int nBase = blockIdx.x * 64;
    int tid = threadIdx.x;
    int tx = tid & 15, ty = tid >> 4;
    const float* Qb = g_Q + (size_t)b * CC * MID;
    const float* Fb = g_FGH + (size_t)b * 192 * HWN;
    float acc[4][4] = {};

#pragma unroll
    for (int r = 0; r < 4; r++) {
        int m = (tid >> 4) + r * 16;
        int k4 = (tid & 15) * 4;
        float4 a = *(const float4*)&Qb[(size_t)(rowBase + m) * MID + k4];
        As2[m][k4 + 0] = a.x; As2[m][k4 + 1] = a.y; As2[m][k4 + 2] = a.z; As2[m][k4 + 3] = a.w;
        float4 bq = *(const float4*)&Fb[(size_t)m * HWN + nBase + k4];
        *(float4*)&Bs2[m][k4] = bq;
    }
    __syncthreads();
#pragma unroll
    for (int k = 0; k < 64; k++) {
        float av[4];
#pragma unroll
        for (int i = 0; i < 4; i++) av[i] = As2[ty * 4 + i][k];
        float4 bq = *(const float4*)&Bs2[k][tx * 4];
        float bw[4] = {bq.x, bq.y, bq.z, bq.w};
#pragma unroll
        for (int i = 0; i < 4; i++)
#pragma unroll
            for (int j = 0; j < 4; j++) acc[i][j] += av[i] * bw[j];
    }
#pragma unroll
    for (int i = 0; i < 4; i++) {
        int orow = rowBase + ty * 4 + i;
        float bias = bv[orow];
        size_t off = ((size_t)b * CC + orow) * HWN + nBase + tx * 4;
        float4 xr = *(const float4*)&x[off];
        float4 v;
        v.x = acc[i][0] + bias + xr.x;
        v.y = acc[i][1] + bias + xr.y;
        v.z = acc[i][2] + bias + xr.z;
        v.w = acc[i][3] + bias + xr.w;
        *(float4*)&out[off] = v;
    }
}

// ---------------- launch ----------------
extern "C" void kernel_launch(void* const* d_in, const int* in_sizes, int n_in,
                              void* d_out, int out_size) {
    (void)in_sizes; (void)n_in; (void)out_size;
    const float* x   = (const float*)d_in[0];
    const float* Wf  = (const float*)d_in[1];
    const float* bf  = (const float*)d_in[2];
    const float* gaf = (const float*)d_in[3];
    const float* bef = (const float*)d_in[4];
    const float* mef = (const float*)d_in[5];
    const float* vaf = (const float*)d_in[6];
    const float* Wg  = (const float*)d_in[7];
    const float* bg  = (const float*)d_in[8];
    const float* gag = (const float*)d_in[9];
    const float* beg = (const float*)d_in[10];
    const float* meg = (const float*)d_in[11];
    const float* vag = (const float*)d_in[12];
    const float* Wh  = (const float*)d_in[13];
    const float* bh  = (const float*)d_in[14];
    const float* Wv  = (const float*)d_in[15];
    const float* bv  = (const float*)d_in[16];
    const float* v0  = (const float*)d_in[17];
    float* out = (float*)d_out;

    k_prep<<<(192 * CC + 255) / 256, 256>>>(Wf, bf, gaf, bef, mef, vaf,
                                            Wg, bg, gag, beg, meg, vag, Wh, bh);
    k_xsplit<<<dim3(HWN / 32, CC / 32, BB), dim3(32, 8)>>>(x);
    k_fgh_mma<<<dim3(HWN / 128, 3, BB), 256>>>();
    k_gv<<<dim3(BB, MID), 128>>>(v0);
    k_vun<<<dim3(HWN / 128, BB), 128>>>();
    k_fvgvv<<<dim3(BB, 128), 128>>>();
    k_s<<<BB, 32>>>();
    k_M<<<dim3(BB, 64), 256>>>();
    k_Q<<<dim3(BB, 64), 256>>>(Wv);
    k_out<<<dim3(HWN / 64, CC / 64, BB), 256>>>(x, bv, out);
}